// round 5
// baseline (speedup 1.0000x reference)
#include <cuda_runtime.h>

#define B_    32
#define N_    8192
#define HD    256     // H_DIM
#define GH    512     // G_HID
#define GD    256     // G_DIM
#define KC    64      // K
#define CHUNK 128     // N_/KC
#define ROWS  129     // 2K+1
#define M_TOT 4128    // B_*ROWS
#define NB    148     // persistent grid = #SMs

typedef unsigned long long u64;

// Scratch (static device globals — no allocation allowed)
__device__ float d_H [M_TOT * HD];   // 4.2 MB
__device__ float d_h1[M_TOT * GH];   // 8.4 MB
__device__ float d_gs[M_TOT * GD];   // 4.2 MB
__device__ float d_Sp[4 * B_ * GD];

// Grid barrier state (generation-based; monotonic gen, no reset race)
__device__ unsigned d_arrive = 0;
__device__ unsigned d_gen    = 0;

__device__ __forceinline__ void gbar() {
    __syncthreads();
    if (threadIdx.x == 0) {
        __threadfence();
        unsigned g   = *(volatile unsigned*)&d_gen;   // read BEFORE arriving
        unsigned old = atomicAdd(&d_arrive, 1u);
        if (old == NB - 1) {
            atomicExch(&d_arrive, 0u);
            __threadfence();
            atomicAdd(&d_gen, 1u);                    // release
        } else {
            while (*(volatile unsigned*)&d_gen == g) { }
        }
        __threadfence();
    }
    __syncthreads();
}

// ---------------------------------------------------------------------------
// packed f32x2 helpers
// ---------------------------------------------------------------------------
__device__ __forceinline__ u64 pk2(float lo, float hi) {
    u64 r;
    asm("mov.b64 %0, {%1, %2};" : "=l"(r) : "f"(lo), "f"(hi));
    return r;
}
__device__ __forceinline__ void ffma2(u64& d, u64 a, u64 b) {
    asm("fma.rn.f32x2 %0, %1, %2, %0;" : "+l"(d) : "l"(a), "l"(b));
}
__device__ __forceinline__ float2 unpk(u64 v) {
    unsigned lo, hi;
    asm("mov.b64 {%0, %1}, %2;" : "=r"(lo), "=r"(hi) : "l"(v));
    return make_float2(__uint_as_float(lo), __uint_as_float(hi));
}

// ---------------------------------------------------------------------------
// GEMM tile (one 128xBN tile per call), duplicated-A smem so the packed
// FFMA2 'a' operand comes straight from LDS.128 (no dup MOVs in inner loop).
// As2 row stride = 2*128+8 = 264 floats; Bs row stride = BN+4.
// ---------------------------------------------------------------------------
#define AS2_STRIDE 264
#define AS2_BUF    (16 * AS2_STRIDE)      // floats per buffer

template<int BN, bool RELU>
__device__ void gemm_tile(const float* A, const float* __restrict__ W,
                          const float* __restrict__ bias, float* C,
                          int M, int Nn, int Ktot, int bx, int by,
                          float* As2, float* Bs)
{
    constexpr int TN  = BN / 16;     // 8 or 4
    constexpr int TN2 = TN / 2;      // 4 or 2
    constexpr int BV  = BN / 64;     // 2 or 1
    constexpr int BSTRIDE = BN + 4;
    constexpr int BBUF = 16 * BSTRIDE;

    const int tid = threadIdx.x;
    const int tx  = tid & 15;
    const int ty  = tid >> 4;
    const int m0  = by * 128;
    const int n0  = bx * BN;

    const int ar = tid >> 1;
    const int ac = (tid & 1) * 8;
    const bool a_ok = (m0 + ar) < M;
    const float* aptr = A + (size_t)(m0 + ar) * Ktot + ac;

    int brow[BV], bcol[BV];
#pragma unroll
    for (int t = 0; t < BV; ++t) {
        const int idx4 = tid + t * 256;
        brow[t] = idx4 / (BN / 4);
        bcol[t] = (idx4 % (BN / 4)) * 4;
    }

    u64 acc[8][TN2];
#pragma unroll
    for (int i = 0; i < 8; ++i)
#pragma unroll
        for (int j = 0; j < TN2; ++j) acc[i][j] = 0ull;

    // prologue
    float4 pa0 = make_float4(0,0,0,0), pa1 = pa0;
    float4 pb[BV];
    if (a_ok) { pa0 = *(const float4*)aptr; pa1 = *(const float4*)(aptr + 4); }
#pragma unroll
    for (int t = 0; t < BV; ++t)
        pb[t] = *(const float4*)(W + (size_t)brow[t] * Nn + n0 + bcol[t]);

    {
        float av[8] = {pa0.x, pa0.y, pa0.z, pa0.w, pa1.x, pa1.y, pa1.z, pa1.w};
#pragma unroll
        for (int j = 0; j < 8; ++j)
            *(float2*)&As2[(ac + j) * AS2_STRIDE + 2 * ar] = make_float2(av[j], av[j]);
#pragma unroll
        for (int t = 0; t < BV; ++t)
            *(float4*)&Bs[brow[t] * BSTRIDE + bcol[t]] = pb[t];
    }
    __syncthreads();

    int buf = 0;
    for (int k0 = 0; k0 < Ktot; k0 += 16) {
        const int k1 = k0 + 16;
        const bool more = (k1 < Ktot);

        if (more) {
            if (a_ok) {
                pa0 = *(const float4*)(aptr + k1);
                pa1 = *(const float4*)(aptr + k1 + 4);
            }
#pragma unroll
            for (int t = 0; t < BV; ++t)
                pb[t] = *(const float4*)(W + (size_t)(k1 + brow[t]) * Nn + n0 + bcol[t]);
        }

        const float* Ab = As2 + buf * AS2_BUF;
        const float* Bb = Bs  + buf * BBUF;
#pragma unroll
        for (int kk = 0; kk < 16; ++kk) {
            const float* arow = Ab + kk * AS2_STRIDE + ty * 16;
            u64 ad[8];
#pragma unroll
            for (int t = 0; t < 4; ++t) {
                float4 q = *(const float4*)(arow + 4 * t);   // dup pairs, LDS.128
                ad[2*t]   = pk2(q.x, q.y);
                ad[2*t+1] = pk2(q.z, q.w);
            }
            const float* browp = Bb + kk * BSTRIDE + tx * TN;
            u64 bv[TN2];
#pragma unroll
            for (int t = 0; t < TN2 / 2; ++t) {
                float4 q = *(const float4*)(browp + 4 * t);
                bv[2*t]   = pk2(q.x, q.y);
                bv[2*t+1] = pk2(q.z, q.w);
            }
#pragma unroll
            for (int i = 0; i < 8; ++i)
#pragma unroll
                for (int j = 0; j < TN2; ++j)
                    ffma2(acc[i][j], ad[i], bv[j]);
        }

        if (more) {
            const int nb = buf ^ 1;
            float* An = As2 + nb * AS2_BUF;
            float* Bn = Bs  + nb * BBUF;
            float av[8] = {pa0.x, pa0.y, pa0.z, pa0.w, pa1.x, pa1.y, pa1.z, pa1.w};
#pragma unroll
            for (int j = 0; j < 8; ++j)
                *(float2*)&An[(ac + j) * AS2_STRIDE + 2 * ar] = make_float2(av[j], av[j]);
#pragma unroll
            for (int t = 0; t < BV; ++t)
                *(float4*)&Bn[brow[t] * BSTRIDE + bcol[t]] = pb[t];
            __syncthreads();
            buf = nb;
        }
    }

    // epilogue
    const int gn0 = n0 + tx * TN;
    float bsv[TN];
#pragma unroll
    for (int j = 0; j < TN; ++j) bsv[j] = bias[gn0 + j];

#pragma unroll
    for (int i = 0; i < 8; ++i) {
        const int gm = m0 + ty * 8 + i;
        if (gm >= M) continue;
        float o[TN];
#pragma unroll
        for (int j = 0; j < TN2; ++j) {
            float2 p = unpk(acc[i][j]);
            o[2*j]   = p.x + bsv[2*j];
            o[2*j+1] = p.y + bsv[2*j+1];
        }
        if (RELU) {
#pragma unroll
            for (int j = 0; j < TN; ++j) o[j] = fmaxf(o[j], 0.f);
        }
        float* cp = C + (size_t)gm * Nn + gn0;
#pragma unroll
        for (int j = 0; j < TN2; j += 2)
            *(float4*)(cp + j * 2) = make_float4(o[2*j], o[2*j+1], o[2*j+2], o[2*j+3]);
    }
    __syncthreads();   // smem safe before any later phase reuse
}

// ---------------------------------------------------------------------------
// Fused persistent kernel: reduce | GEMM1 | GEMM2 | S | finalize
// ---------------------------------------------------------------------------
__global__ __launch_bounds__(256, 1)
void fused_kernel(const float* __restrict__ hs,
                  const int*   __restrict__ cs,
                  const int*   __restrict__ np,
                  const float* __restrict__ W1, const float* __restrict__ b1,
                  const float* __restrict__ W2, const float* __restrict__ b2,
                  float* __restrict__ out)
{
    extern __shared__ float smem_f[];
    const int bid = blockIdx.x;
    const int tid = threadIdx.x;

    // ---------------- Phase A: clustered reduce ----------------
    {
        int*    scs = (int*)smem_f;             // 128 ints
        float4* sm  = (float4*)(smem_f + 256);  // 256 float4
        const int n    = np[0];
        const int lane = tid & 63;
        const int grp  = tid >> 6;

        for (int pair = bid; pair < KC * B_; pair += NB) {
            const int k = pair & (KC - 1);
            const int b = pair >> 6;
            __syncthreads();
            if (tid < CHUNK) scs[tid] = cs[k * CHUNK + tid];
            __syncthreads();

            const int base = k * CHUNK;
            const float* p = hs + ((size_t)b * N_ + base) * HD + lane * 4;
            float4 s = make_float4(0.f, 0.f, 0.f, 0.f);
#pragma unroll 8
            for (int i = grp; i < CHUNK; i += 4) {
                float4 v = *(const float4*)(p + (size_t)i * HD);  // unconditional
                if (((base + i) < n) & (scs[i] == k)) {
                    s.x += v.x; s.y += v.y; s.z += v.z; s.w += v.w;
                }
            }
            sm[grp * 64 + lane] = s;
            __syncthreads();

            if (grp == 0) {
                float4 t  = sm[lane];
                float4 u1 = sm[64 + lane], u2 = sm[128 + lane], u3 = sm[192 + lane];
                t.x += u1.x + u2.x + u3.x;
                t.y += u1.y + u2.y + u3.y;
                t.z += u1.z + u2.z + u3.z;
                t.w += u1.w + u2.w + u3.w;

                float4 hv = *(const float4*)(hs + ((size_t)b * N_ + n) * HD + lane * 4);

                ((float4*)(d_H + (size_t)(b * ROWS + k)      * HD))[lane] = t;
                ((float4*)(d_H + (size_t)(b * ROWS + KC + k) * HD))[lane] =
                    make_float4(t.x + hv.x, t.y + hv.y, t.z + hv.z, t.w + hv.w);
                if (k == 0)
                    ((float4*)(d_H + (size_t)(b * ROWS + 2 * KC) * HD))[lane] = hv;
            }
        }
    }
    gbar();

    // ---------------- Phase B: GEMM1 (relu) ----------------
    if (bid < 132)
        gemm_tile<128, true>(d_H, W1, b1, d_h1, M_TOT, GH, HD,
                             bid & 3, bid >> 2, smem_f, smem_f + 2 * AS2_BUF);
    gbar();

    // ---------------- Phase C: GEMM2 ----------------
    if (bid < 132)
        gemm_tile<64, false>(d_h1, W2, b2, d_gs, M_TOT, GD, GH,
                             bid & 3, bid >> 2, smem_f, smem_f + 2 * AS2_BUF);
    gbar();

    // ---------------- Phase D1: S partials ----------------
    if (bid < 128) {
        const int q = bid >> 5;
        const int b = bid & 31;
        const float* g = d_gs + (size_t)b * ROWS * GD;
        float s = 0.f;
#pragma unroll
        for (int j = q * 16; j < q * 16 + 16; ++j)
            s += g[(size_t)j * GD + tid];
        d_Sp[((size_t)q * B_ + b) * GD + tid] = s;
    }
    gbar();

    // ---------------- Phase D2: finalize ----------------
    for (int idx = bid; idx < (KC + 1) * B_; idx += NB) {
        const int b = idx & 31;
        const int k = idx >> 5;   // 0..64

        float S = d_Sp[((size_t)0 * B_ + b) * GD + tid]
                + d_Sp[((size_t)1 * B_ + b) * GD + tid]
                + d_Sp[((size_t)2 * B_ + b) * GD + tid]
                + d_Sp[((size_t)3 * B_ + b) * GD + tid];

        const float* g = d_gs + (size_t)b * ROWS * GD;
        float v;
        if (k < KC)
            v = S - g[(size_t)k * GD + tid] + g[(size_t)(KC + k) * GD + tid];
        else
            v = S + g[(size_t)(2 * KC) * GD + tid];
        out[((size_t)b * (KC + 1) + k) * GD + tid] = v;

        if (tid == 0)
            out[(size_t)B_ * (KC + 1) * GD + b * (KC + 1) + k] = 1.0f;  // mask
    }
}

// ---------------------------------------------------------------------------
#define SMEM_BYTES ((2 * AS2_BUF + 2 * 16 * 132) * 4)   // 50688 B

extern "C" void kernel_launch(void* const* d_in, const int* in_sizes, int n_in,
                              void* d_out, int out_size)
{
    const float* hs = (const float*)d_in[0];
    const int*   cs = (const int*)  d_in[1];
    const float* W1 = (const float*)d_in[2];
    const float* b1 = (const float*)d_in[3];
    const float* W2 = (const float*)d_in[4];
    const float* b2 = (const float*)d_in[5];
    const int*   np = (const int*)  d_in[6];
    float* out = (float*)d_out;

    static bool attr_set = false;
    if (!attr_set) {
        cudaFuncSetAttribute(fused_kernel,
                             cudaFuncAttributeMaxDynamicSharedMemorySize, SMEM_BYTES);
        attr_set = true;
    }

    fused_kernel<<<NB, 256, SMEM_BYTES>>>(hs, cs, np, W1, b1, W2, b2, out);
}

// round 6
// speedup vs baseline: 1.0129x; 1.0129x over previous
#include <cuda_runtime.h>

#define B_    32
#define N_    8192
#define HD    256     // H_DIM
#define GH    512     // G_HID
#define GD    256     // G_DIM
#define KC    64      // K
#define CHUNK 128     // N_/KC
#define ROWS  129     // 2K+1
#define M_TOT 4128    // B_*ROWS
#define NB    148     // persistent grid = #SMs

typedef unsigned long long u64;

// Scratch (static device globals — no allocation allowed)
__device__ float d_H [M_TOT * HD];   // 4.2 MB
__device__ float d_h1[M_TOT * GH];   // 8.4 MB
__device__ float d_gs[M_TOT * GD];   // 4.2 MB
__device__ float d_Sp[4 * B_ * GD];

// Grid barrier state (generation-based; monotonic gen, no reset race)
__device__ unsigned d_arrive = 0;
__device__ unsigned d_gen    = 0;

__device__ __forceinline__ void gbar() {
    __syncthreads();
    if (threadIdx.x == 0) {
        __threadfence();
        unsigned g   = *(volatile unsigned*)&d_gen;   // read BEFORE arriving
        unsigned old = atomicAdd(&d_arrive, 1u);
        if (old == NB - 1) {
            atomicExch(&d_arrive, 0u);
            __threadfence();
            atomicAdd(&d_gen, 1u);                    // release
        } else {
            while (*(volatile unsigned*)&d_gen == g) { }
        }
        __threadfence();
    }
    __syncthreads();
}

// ---------------------------------------------------------------------------
// packed f32x2 helpers
// ---------------------------------------------------------------------------
__device__ __forceinline__ u64 pk2(float lo, float hi) {
    u64 r;
    asm("mov.b64 %0, {%1, %2};" : "=l"(r) : "f"(lo), "f"(hi));
    return r;
}
__device__ __forceinline__ void ffma2(u64& d, u64 a, u64 b) {
    asm("fma.rn.f32x2 %0, %1, %2, %0;" : "+l"(d) : "l"(a), "l"(b));
}
__device__ __forceinline__ float2 unpk(u64 v) {
    unsigned lo, hi;
    asm("mov.b64 {%0, %1}, %2;" : "=r"(lo), "=r"(hi) : "l"(v));
    return make_float2(__uint_as_float(lo), __uint_as_float(hi));
}

// ---------------------------------------------------------------------------
// GEMM tile (one 128xBN tile per call), duplicated-A smem so the packed
// FFMA2 'a' operand comes straight from LDS.128 (no dup MOVs in inner loop).
// As2 row stride = 2*128+8 = 264 floats; Bs row stride = BN+4.
// ---------------------------------------------------------------------------
#define AS2_STRIDE 264
#define AS2_BUF    (16 * AS2_STRIDE)      // floats per buffer

template<int BN, bool RELU>
__device__ void gemm_tile(const float* A, const float* __restrict__ W,
                          const float* __restrict__ bias, float* C,
                          int M, int Nn, int Ktot, int bx, int by,
                          float* As2, float* Bs)
{
    constexpr int TN  = BN / 16;     // 8 or 4
    constexpr int TN2 = TN / 2;      // 4 or 2
    constexpr int BV  = BN / 64;     // 2 or 1
    constexpr int BSTRIDE = BN + 4;
    constexpr int BBUF = 16 * BSTRIDE;

    const int tid = threadIdx.x;
    const int tx  = tid & 15;
    const int ty  = tid >> 4;
    const int m0  = by * 128;
    const int n0  = bx * BN;

    const int ar = tid >> 1;
    const int ac = (tid & 1) * 8;
    const bool a_ok = (m0 + ar) < M;
    const float* aptr = A + (size_t)(m0 + ar) * Ktot + ac;

    int brow[BV], bcol[BV];
#pragma unroll
    for (int t = 0; t < BV; ++t) {
        const int idx4 = tid + t * 256;
        brow[t] = idx4 / (BN / 4);
        bcol[t] = (idx4 % (BN / 4)) * 4;
    }

    u64 acc[8][TN2];
#pragma unroll
    for (int i = 0; i < 8; ++i)
#pragma unroll
        for (int j = 0; j < TN2; ++j) acc[i][j] = 0ull;

    // prologue
    float4 pa0 = make_float4(0,0,0,0), pa1 = pa0;
    float4 pb[BV];
    if (a_ok) { pa0 = *(const float4*)aptr; pa1 = *(const float4*)(aptr + 4); }
#pragma unroll
    for (int t = 0; t < BV; ++t)
        pb[t] = *(const float4*)(W + (size_t)brow[t] * Nn + n0 + bcol[t]);

    {
        float av[8] = {pa0.x, pa0.y, pa0.z, pa0.w, pa1.x, pa1.y, pa1.z, pa1.w};
#pragma unroll
        for (int j = 0; j < 8; ++j)
            *(float2*)&As2[(ac + j) * AS2_STRIDE + 2 * ar] = make_float2(av[j], av[j]);
#pragma unroll
        for (int t = 0; t < BV; ++t)
            *(float4*)&Bs[brow[t] * BSTRIDE + bcol[t]] = pb[t];
    }
    __syncthreads();

    int buf = 0;
    for (int k0 = 0; k0 < Ktot; k0 += 16) {
        const int k1 = k0 + 16;
        const bool more = (k1 < Ktot);

        if (more) {
            if (a_ok) {
                pa0 = *(const float4*)(aptr + k1);
                pa1 = *(const float4*)(aptr + k1 + 4);
            }
#pragma unroll
            for (int t = 0; t < BV; ++t)
                pb[t] = *(const float4*)(W + (size_t)(k1 + brow[t]) * Nn + n0 + bcol[t]);
        }

        const float* Ab = As2 + buf * AS2_BUF;
        const float* Bb = Bs  + buf * BBUF;
#pragma unroll
        for (int kk = 0; kk < 16; ++kk) {
            const float* arow = Ab + kk * AS2_STRIDE + ty * 16;
            u64 ad[8];
#pragma unroll
            for (int t = 0; t < 4; ++t) {
                float4 q = *(const float4*)(arow + 4 * t);   // dup pairs, LDS.128
                ad[2*t]   = pk2(q.x, q.y);
                ad[2*t+1] = pk2(q.z, q.w);
            }
            const float* browp = Bb + kk * BSTRIDE + tx * TN;
            u64 bv[TN2];
#pragma unroll
            for (int t = 0; t < TN2 / 2; ++t) {
                float4 q = *(const float4*)(browp + 4 * t);
                bv[2*t]   = pk2(q.x, q.y);
                bv[2*t+1] = pk2(q.z, q.w);
            }
#pragma unroll
            for (int i = 0; i < 8; ++i)
#pragma unroll
                for (int j = 0; j < TN2; ++j)
                    ffma2(acc[i][j], ad[i], bv[j]);
        }

        if (more) {
            const int nb = buf ^ 1;
            float* An = As2 + nb * AS2_BUF;
            float* Bn = Bs  + nb * BBUF;
            float av[8] = {pa0.x, pa0.y, pa0.z, pa0.w, pa1.x, pa1.y, pa1.z, pa1.w};
#pragma unroll
            for (int j = 0; j < 8; ++j)
                *(float2*)&An[(ac + j) * AS2_STRIDE + 2 * ar] = make_float2(av[j], av[j]);
#pragma unroll
            for (int t = 0; t < BV; ++t)
                *(float4*)&Bn[brow[t] * BSTRIDE + bcol[t]] = pb[t];
            __syncthreads();
            buf = nb;
        }
    }

    // epilogue
    const int gn0 = n0 + tx * TN;
    float bsv[TN];
#pragma unroll
    for (int j = 0; j < TN; ++j) bsv[j] = bias[gn0 + j];

#pragma unroll
    for (int i = 0; i < 8; ++i) {
        const int gm = m0 + ty * 8 + i;
        if (gm >= M) continue;
        float o[TN];
#pragma unroll
        for (int j = 0; j < TN2; ++j) {
            float2 p = unpk(acc[i][j]);
            o[2*j]   = p.x + bsv[2*j];
            o[2*j+1] = p.y + bsv[2*j+1];
        }
        if (RELU) {
#pragma unroll
            for (int j = 0; j < TN; ++j) o[j] = fmaxf(o[j], 0.f);
        }
        float* cp = C + (size_t)gm * Nn + gn0;
#pragma unroll
        for (int j = 0; j < TN2; j += 2)
            *(float4*)(cp + j * 2) = make_float4(o[2*j], o[2*j+1], o[2*j+2], o[2*j+3]);
    }
    __syncthreads();   // smem safe before any later phase reuse
}

// ---------------------------------------------------------------------------
// Fused persistent kernel: reduce | GEMM1 | GEMM2 | S | finalize
// ---------------------------------------------------------------------------
__global__ __launch_bounds__(256, 1)
void fused_kernel(const float* __restrict__ hs,
                  const int*   __restrict__ cs,
                  const int*   __restrict__ np,
                  const float* __restrict__ W1, const float* __restrict__ b1,
                  const float* __restrict__ W2, const float* __restrict__ b2,
                  float* __restrict__ out)
{
    extern __shared__ float smem_f[];
    const int bid = blockIdx.x;
    const int tid = threadIdx.x;

    // ---------------- Phase A: clustered reduce ----------------
    {
        int*    scs = (int*)smem_f;             // 128 ints
        float4* sm  = (float4*)(smem_f + 256);  // 256 float4
        const int n    = np[0];
        const int lane = tid & 63;
        const int grp  = tid >> 6;

        for (int pair = bid; pair < KC * B_; pair += NB) {
            const int k = pair & (KC - 1);
            const int b = pair >> 6;
            __syncthreads();
            if (tid < CHUNK) scs[tid] = cs[k * CHUNK + tid];
            __syncthreads();

            const int base = k * CHUNK;
            const float* p = hs + ((size_t)b * N_ + base) * HD + lane * 4;
            float4 s = make_float4(0.f, 0.f, 0.f, 0.f);
#pragma unroll 8
            for (int i = grp; i < CHUNK; i += 4) {
                float4 v = *(const float4*)(p + (size_t)i * HD);  // unconditional
                if (((base + i) < n) & (scs[i] == k)) {
                    s.x += v.x; s.y += v.y; s.z += v.z; s.w += v.w;
                }
            }
            sm[grp * 64 + lane] = s;
            __syncthreads();

            if (grp == 0) {
                float4 t  = sm[lane];
                float4 u1 = sm[64 + lane], u2 = sm[128 + lane], u3 = sm[192 + lane];
                t.x += u1.x + u2.x + u3.x;
                t.y += u1.y + u2.y + u3.y;
                t.z += u1.z + u2.z + u3.z;
                t.w += u1.w + u2.w + u3.w;

                float4 hv = *(const float4*)(hs + ((size_t)b * N_ + n) * HD + lane * 4);

                ((float4*)(d_H + (size_t)(b * ROWS + k)      * HD))[lane] = t;
                ((float4*)(d_H + (size_t)(b * ROWS + KC + k) * HD))[lane] =
                    make_float4(t.x + hv.x, t.y + hv.y, t.z + hv.z, t.w + hv.w);
                if (k == 0)
                    ((float4*)(d_H + (size_t)(b * ROWS + 2 * KC) * HD))[lane] = hv;
            }
        }
    }
    gbar();

    // ---------------- Phase B: GEMM1 (relu) ----------------
    if (bid < 132)
        gemm_tile<128, true>(d_H, W1, b1, d_h1, M_TOT, GH, HD,
                             bid & 3, bid >> 2, smem_f, smem_f + 2 * AS2_BUF);
    gbar();

    // ---------------- Phase C: GEMM2 ----------------
    if (bid < 132)
        gemm_tile<64, false>(d_h1, W2, b2, d_gs, M_TOT, GD, GH,
                             bid & 3, bid >> 2, smem_f, smem_f + 2 * AS2_BUF);
    gbar();

    // ---------------- Phase D1: S partials ----------------
    if (bid < 128) {
        const int q = bid >> 5;
        const int b = bid & 31;
        const float* g = d_gs + (size_t)b * ROWS * GD;
        float s = 0.f;
#pragma unroll
        for (int j = q * 16; j < q * 16 + 16; ++j)
            s += g[(size_t)j * GD + tid];
        d_Sp[((size_t)q * B_ + b) * GD + tid] = s;
    }
    gbar();

    // ---------------- Phase D2: finalize ----------------
    for (int idx = bid; idx < (KC + 1) * B_; idx += NB) {
        const int b = idx & 31;
        const int k = idx >> 5;   // 0..64

        float S = d_Sp[((size_t)0 * B_ + b) * GD + tid]
                + d_Sp[((size_t)1 * B_ + b) * GD + tid]
                + d_Sp[((size_t)2 * B_ + b) * GD + tid]
                + d_Sp[((size_t)3 * B_ + b) * GD + tid];

        const float* g = d_gs + (size_t)b * ROWS * GD;
        float v;
        if (k < KC)
            v = S - g[(size_t)k * GD + tid] + g[(size_t)(KC + k) * GD + tid];
        else
            v = S + g[(size_t)(2 * KC) * GD + tid];
        out[((size_t)b * (KC + 1) + k) * GD + tid] = v;

        if (tid == 0)
            out[(size_t)B_ * (KC + 1) * GD + b * (KC + 1) + k] = 1.0f;  // mask
    }
}

// ---------------------------------------------------------------------------
#define SMEM_BYTES ((2 * AS2_BUF + 2 * 16 * 132) * 4)   // 50688 B

extern "C" void kernel_launch(void* const* d_in, const int* in_sizes, int n_in,
                              void* d_out, int out_size)
{
    const float* hs = (const float*)d_in[0];
    const int*   cs = (const int*)  d_in[1];
    const float* W1 = (const float*)d_in[2];
    const float* b1 = (const float*)d_in[3];
    const float* W2 = (const float*)d_in[4];
    const float* b2 = (const float*)d_in[5];
    const int*   np = (const int*)  d_in[6];
    float* out = (float*)d_out;

    static bool attr_set = false;
    if (!attr_set) {
        cudaFuncSetAttribute(fused_kernel,
                             cudaFuncAttributeMaxDynamicSharedMemorySize, SMEM_BYTES);
        attr_set = true;
    }

    fused_kernel<<<NB, 256, SMEM_BYTES>>>(hs, cs, np, W1, b1, W2, b2, out);
}

// round 7
// speedup vs baseline: 1.5541x; 1.5343x over previous
#include <cuda_runtime.h>

#define B_    32
#define N_    8192
#define HD    256     // H_DIM
#define GH    512     // G_HID
#define GD    256     // G_DIM
#define KC    64      // K
#define CHUNK 128     // N_/KC
#define ROWS  129     // 2K+1
#define M_TOT 4128    // B_*ROWS

typedef unsigned long long u64;

// Scratch (static device globals — no allocation allowed)
__device__ float d_H [M_TOT * HD];   // 4.2 MB
__device__ float d_h1[M_TOT * GH];   // 8.4 MB
__device__ float d_gs[M_TOT * GD];   // 4.2 MB
__device__ float d_Sp[4 * B_ * GD];

// ---------------------------------------------------------------------------
// packed f32x2 helpers (FFMA2 is PTX-only; ptxas never auto-fuses)
// ---------------------------------------------------------------------------
__device__ __forceinline__ u64 dup2(float x) {
    unsigned xi = __float_as_uint(x);
    u64 r;
    asm("mov.b64 %0, {%1, %1};" : "=l"(r) : "r"(xi));
    return r;
}
__device__ __forceinline__ void ffma2(u64& d, u64 a, u64 b) {
    asm("fma.rn.f32x2 %0, %1, %2, %0;" : "+l"(d) : "l"(a), "l"(b));
}
__device__ __forceinline__ float2 unpk(u64 v) {
    unsigned lo, hi;
    asm("mov.b64 {%0, %1}, %2;" : "=r"(lo), "=r"(hi) : "l"(v));
    return make_float2(__uint_as_float(lo), __uint_as_float(hi));
}

// ---------------------------------------------------------------------------
// Kernel 0: mask (placed first so idx3 of the launch sequence = gemm2)
// ---------------------------------------------------------------------------
__global__ void mask_kernel(float* __restrict__ out)
{
    float* mask = out + (size_t)B_ * (KC + 1) * GD;
    for (int i = threadIdx.x; i < B_ * (KC + 1); i += blockDim.x)
        mask[i] = 1.0f;
}

// ---------------------------------------------------------------------------
// Kernel 1: clustered reduction. Grid (K, B), 512 threads (8 row-groups).
// cs staged to smem; hs float4 loads unconditional (front-batched, MLP=16);
// predicate applies only to the adds.
// ---------------------------------------------------------------------------
__global__ __launch_bounds__(512)
void reduce_kernel(const float* __restrict__ hs,
                   const int*   __restrict__ cs,
                   const int*   __restrict__ n_ptr)
{
    const int k    = blockIdx.x;
    const int b    = blockIdx.y;
    const int tid  = threadIdx.x;
    const int lane = tid & 63;    // h/4
    const int grp  = tid >> 6;    // 0..7
    const int base = k * CHUNK;

    __shared__ int    scs[CHUNK];
    __shared__ int    sn;
    __shared__ float4 sm[8][64];

    if (tid < CHUNK) scs[tid] = cs[base + tid];
    if (tid == 0)    sn = *n_ptr;
    __syncthreads();

    const int n = sn;
    const float* p = hs + ((size_t)b * N_ + base) * HD + lane * 4;

    float4 s = make_float4(0.f, 0.f, 0.f, 0.f);
#pragma unroll 16
    for (int i = grp; i < CHUNK; i += 8) {
        float4 v = *(const float4*)(p + (size_t)i * HD);   // always in-bounds
        if (((base + i) < n) & (scs[i] == k)) {
            s.x += v.x; s.y += v.y; s.z += v.z; s.w += v.w;
        }
    }
    sm[grp][lane] = s;
    __syncthreads();

    if (grp == 0) {
        float4 t = sm[0][lane];
#pragma unroll
        for (int g = 1; g < 8; ++g) {
            float4 u = sm[g][lane];
            t.x += u.x; t.y += u.y; t.z += u.z; t.w += u.w;
        }
        float4 hv = *(const float4*)(hs + ((size_t)b * N_ + n) * HD + lane * 4);

        ((float4*)(d_H + (size_t)(b * ROWS + k)      * HD))[lane] = t;
        ((float4*)(d_H + (size_t)(b * ROWS + KC + k) * HD))[lane] =
            make_float4(t.x + hv.x, t.y + hv.y, t.z + hv.z, t.w + hv.w);
        if (k == 0)
            ((float4*)(d_H + (size_t)(b * ROWS + 2 * KC) * HD))[lane] = hv;
    }
}

// ---------------------------------------------------------------------------
// Kernels 2/3: fp32 GEMM, 128 x BN tile, BK=16, 256 threads, double-buffered
// smem with register prefetch, packed f32x2 accumulators.
// BN=128 -> 8x8 per thread; BN=64 -> 8x4 per thread.
// ---------------------------------------------------------------------------
template<int BN, bool RELU>
__global__ __launch_bounds__(256)
void gemm_kernel(const float* __restrict__ A,
                 const float* __restrict__ W,
                 const float* __restrict__ bias,
                 float* __restrict__ C,
                 int M, int Nn, int Ktot)
{
    constexpr int BM = 128, BK = 16;
    constexpr int TN  = BN / 16;
    constexpr int TN2 = TN / 2;
    constexpr int BV  = BN / 64;

    __shared__ float As[2][BK][BM + 4];
    __shared__ float Bs[2][BK][BN + 4];

    const int tid = threadIdx.x;
    const int tx  = tid & 15;
    const int ty  = tid >> 4;
    const int m0  = blockIdx.y * BM;
    const int n0  = blockIdx.x * BN;

    const int ar = tid >> 1;
    const int ac = (tid & 1) * 8;
    const bool a_ok = (m0 + ar) < M;
    const float* aptr = A + (size_t)(m0 + ar) * Ktot + ac;

    int brow[BV], bcol[BV];
#pragma unroll
    for (int t = 0; t < BV; ++t) {
        const int idx4 = tid + t * 256;
        brow[t] = idx4 / (BN / 4);
        bcol[t] = (idx4 % (BN / 4)) * 4;
    }

    u64 acc[8][TN2];
#pragma unroll
    for (int i = 0; i < 8; ++i)
#pragma unroll
        for (int j = 0; j < TN2; ++j) acc[i][j] = 0ull;

    float4 pa0 = make_float4(0,0,0,0), pa1 = pa0;
    float4 pb[BV];
    if (a_ok) { pa0 = *(const float4*)aptr; pa1 = *(const float4*)(aptr + 4); }
#pragma unroll
    for (int t = 0; t < BV; ++t)
        pb[t] = *(const float4*)(W + (size_t)brow[t] * Nn + n0 + bcol[t]);

    As[0][ac+0][ar] = pa0.x; As[0][ac+1][ar] = pa0.y;
    As[0][ac+2][ar] = pa0.z; As[0][ac+3][ar] = pa0.w;
    As[0][ac+4][ar] = pa1.x; As[0][ac+5][ar] = pa1.y;
    As[0][ac+6][ar] = pa1.z; As[0][ac+7][ar] = pa1.w;
#pragma unroll
    for (int t = 0; t < BV; ++t)
        *(float4*)&Bs[0][brow[t]][bcol[t]] = pb[t];
    __syncthreads();

    int buf = 0;
    for (int k0 = 0; k0 < Ktot; k0 += BK) {
        const int k1 = k0 + BK;
        const bool more = (k1 < Ktot);

        if (more) {
            if (a_ok) {
                pa0 = *(const float4*)(aptr + k1);
                pa1 = *(const float4*)(aptr + k1 + 4);
            }
#pragma unroll
            for (int t = 0; t < BV; ++t)
                pb[t] = *(const float4*)(W + (size_t)(k1 + brow[t]) * Nn + n0 + bcol[t]);
        }

#pragma unroll
        for (int kk = 0; kk < BK; ++kk) {
            float4 a0 = *(const float4*)&As[buf][kk][ty * 8];
            float4 a1 = *(const float4*)&As[buf][kk][ty * 8 + 4];
            const u64* bp = (const u64*)&Bs[buf][kk][tx * TN];
            u64 breg[TN2];
#pragma unroll
            for (int j = 0; j < TN2; ++j) breg[j] = bp[j];

            const float av[8] = {a0.x, a0.y, a0.z, a0.w, a1.x, a1.y, a1.z, a1.w};
#pragma unroll
            for (int i = 0; i < 8; ++i) {
                const u64 ad = dup2(av[i]);
#pragma unroll
                for (int j = 0; j < TN2; ++j) ffma2(acc[i][j], ad, breg[j]);
            }
        }

        if (more) {
            const int nb = buf ^ 1;
            As[nb][ac+0][ar] = pa0.x; As[nb][ac+1][ar] = pa0.y;
            As[nb][ac+2][ar] = pa0.z; As[nb][ac+3][ar] = pa0.w;
            As[nb][ac+4][ar] = pa1.x; As[nb][ac+5][ar] = pa1.y;
            As[nb][ac+6][ar] = pa1.z; As[nb][ac+7][ar] = pa1.w;
#pragma unroll
            for (int t = 0; t < BV; ++t)
                *(float4*)&Bs[nb][brow[t]][bcol[t]] = pb[t];
            __syncthreads();
            buf = nb;
        }
    }

    const int gn0 = n0 + tx * TN;
    float bsv[TN];
#pragma unroll
    for (int j = 0; j < TN; ++j) bsv[j] = bias[gn0 + j];

#pragma unroll
    for (int i = 0; i < 8; ++i) {
        const int gm = m0 + ty * 8 + i;
        if (gm >= M) continue;
        float o[TN];
#pragma unroll
        for (int j = 0; j < TN2; ++j) {
            float2 p = unpk(acc[i][j]);
            o[2*j]   = p.x + bsv[2*j];
            o[2*j+1] = p.y + bsv[2*j+1];
        }
        if (RELU) {
#pragma unroll
            for (int j = 0; j < TN; ++j) o[j] = fmaxf(o[j], 0.f);
        }
        float* cp = C + (size_t)gm * Nn + gn0;
#pragma unroll
        for (int j = 0; j < TN2; j += 2)
            *(float4*)(cp + j * 2) = make_float4(o[2*j], o[2*j+1], o[2*j+2], o[2*j+3]);
    }
}

// ---------------------------------------------------------------------------
// Kernel 4: partial S. Grid (4, B). Block (q,b) sums gs rows q*16..q*16+15.
// ---------------------------------------------------------------------------
__global__ void s_partial_kernel()
{
    const int q = blockIdx.x;
    const int b = blockIdx.y;
    const int h = threadIdx.x;
    const float* g = d_gs + (size_t)b * ROWS * GD;

    float s = 0.f;
#pragma unroll
    for (int j = q * 16; j < q * 16 + 16; ++j)
        s += g[(size_t)j * GD + h];
    d_Sp[((size_t)q * B_ + b) * GD + h] = s;
}

// ---------------------------------------------------------------------------
// Kernel 5: finalize. Grid (K+1, B), 256 threads.
// ---------------------------------------------------------------------------
__global__ void finalize_kernel(float* __restrict__ out)
{
    const int k = blockIdx.x;     // 0..K
    const int b = blockIdx.y;
    const int h = threadIdx.x;

    float S = d_Sp[((size_t)0 * B_ + b) * GD + h]
            + d_Sp[((size_t)1 * B_ + b) * GD + h]
            + d_Sp[((size_t)2 * B_ + b) * GD + h]
            + d_Sp[((size_t)3 * B_ + b) * GD + h];

    const float* g = d_gs + (size_t)b * ROWS * GD;

    float v;
    if (k < KC)
        v = S - g[(size_t)k * GD + h] + g[(size_t)(KC + k) * GD + h];
    else
        v = S + g[(size_t)(2 * KC) * GD + h];
    out[((size_t)b * (KC + 1) + k) * GD + h] = v;
}

// ---------------------------------------------------------------------------
extern "C" void kernel_launch(void* const* d_in, const int* in_sizes, int n_in,
                              void* d_out, int out_size)
{
    const float* hs = (const float*)d_in[0];
    const int*   cs = (const int*)  d_in[1];
    const float* W1 = (const float*)d_in[2];
    const float* b1 = (const float*)d_in[3];
    const float* W2 = (const float*)d_in[4];
    const float* b2 = (const float*)d_in[5];
    const int*   np = (const int*)  d_in[6];
    float* out = (float*)d_out;

    float *pH, *pH1, *pGS;
    cudaGetSymbolAddress((void**)&pH,  d_H);
    cudaGetSymbolAddress((void**)&pH1, d_h1);
    cudaGetSymbolAddress((void**)&pGS, d_gs);

    // idx0: mask
    mask_kernel<<<1, 256>>>(out);

    // idx1: clustered reduce + H materialization
    reduce_kernel<<<dim3(KC, B_), 512>>>(hs, cs, np);

    // idx2: layer 1 [4128,256]@[256,512]+b1, relu (128x128 tiles, 132 blocks)
    gemm_kernel<128, true ><<<dim3(GH / 128, (M_TOT + 127) / 128), 256>>>(pH,  W1, b1, pH1, M_TOT, GH, HD);

    // idx3: layer 2 [4128,512]@[512,256]+b2 (128x64 tiles, 132 blocks)  <- profiled slot
    gemm_kernel<64, false><<<dim3(GD / 64, (M_TOT + 127) / 128), 256>>>(pH1, W2, b2, pGS, M_TOT, GD, GH);

    // idx4: S partials
    s_partial_kernel<<<dim3(4, B_), 256>>>();

    // idx5: finalize
    finalize_kernel<<<dim3(KC + 1, B_), 256>>>(out);
}

// round 8
// speedup vs baseline: 1.5696x; 1.0100x over previous
#include <cuda_runtime.h>

#define B_    32
#define N_    8192
#define HD    256     // H_DIM
#define GH    512     // G_HID
#define GD    256     // G_DIM
#define KC    64      // K
#define CHUNK 128     // N_/KC
#define ROWS  129     // 2K+1
#define M_TOT 4128    // B_*ROWS

typedef unsigned long long u64;

// Scratch (static device globals — no allocation allowed)
__device__ float d_H [M_TOT * HD];   // 4.2 MB
__device__ float d_h1[M_TOT * GH];   // 8.4 MB
__device__ float d_gs[M_TOT * GD];   // 4.2 MB
__device__ float d_Sp[4 * B_ * GD];

// ---------------------------------------------------------------------------
// packed f32x2 helpers (FFMA2 is PTX-only; ptxas never auto-fuses)
// ---------------------------------------------------------------------------
__device__ __forceinline__ u64 dup2(float x) {
    unsigned xi = __float_as_uint(x);
    u64 r;
    asm("mov.b64 %0, {%1, %1};" : "=l"(r) : "r"(xi));
    return r;
}
__device__ __forceinline__ void ffma2(u64& d, u64 a, u64 b) {
    asm("fma.rn.f32x2 %0, %1, %2, %0;" : "+l"(d) : "l"(a), "l"(b));
}
__device__ __forceinline__ float2 unpk(u64 v) {
    unsigned lo, hi;
    asm("mov.b64 {%0, %1}, %2;" : "=r"(lo), "=r"(hi) : "l"(v));
    return make_float2(__uint_as_float(lo), __uint_as_float(hi));
}

// ---------------------------------------------------------------------------
// Kernel 0: mask (placed first so idx3 of the launch sequence = gemm2)
// ---------------------------------------------------------------------------
__global__ void mask_kernel(float* __restrict__ out)
{
    float* mask = out + (size_t)B_ * (KC + 1) * GD;
    for (int i = threadIdx.x; i < B_ * (KC + 1); i += blockDim.x)
        mask[i] = 1.0f;
}

// ---------------------------------------------------------------------------
// Kernel 1: clustered reduction. Grid (K, B), 512 threads (8 row-groups).
// cs staged to smem; hs float4 loads unconditional (front-batched, MLP=16);
// predicate applies only to the adds.
// ---------------------------------------------------------------------------
__global__ __launch_bounds__(512)
void reduce_kernel(const float* __restrict__ hs,
                   const int*   __restrict__ cs,
                   const int*   __restrict__ n_ptr)
{
    const int k    = blockIdx.x;
    const int b    = blockIdx.y;
    const int tid  = threadIdx.x;
    const int lane = tid & 63;    // h/4
    const int grp  = tid >> 6;    // 0..7
    const int base = k * CHUNK;

    __shared__ int    scs[CHUNK];
    __shared__ int    sn;
    __shared__ float4 sm[8][64];

    if (tid < CHUNK) scs[tid] = cs[base + tid];
    if (tid == 0)    sn = *n_ptr;
    __syncthreads();

    const int n = sn;
    const float* p = hs + ((size_t)b * N_ + base) * HD + lane * 4;

    float4 s = make_float4(0.f, 0.f, 0.f, 0.f);
#pragma unroll 16
    for (int i = grp; i < CHUNK; i += 8) {
        float4 v = *(const float4*)(p + (size_t)i * HD);   // always in-bounds
        if (((base + i) < n) & (scs[i] == k)) {
            s.x += v.x; s.y += v.y; s.z += v.z; s.w += v.w;
        }
    }
    sm[grp][lane] = s;
    __syncthreads();

    if (grp == 0) {
        float4 t = sm[0][lane];
#pragma unroll
        for (int g = 1; g < 8; ++g) {
            float4 u = sm[g][lane];
            t.x += u.x; t.y += u.y; t.z += u.z; t.w += u.w;
        }
        float4 hv = *(const float4*)(hs + ((size_t)b * N_ + n) * HD + lane * 4);

        ((float4*)(d_H + (size_t)(b * ROWS + k)      * HD))[lane] = t;
        ((float4*)(d_H + (size_t)(b * ROWS + KC + k) * HD))[lane] =
            make_float4(t.x + hv.x, t.y + hv.y, t.z + hv.z, t.w + hv.w);
        if (k == 0)
            ((float4*)(d_H + (size_t)(b * ROWS + 2 * KC) * HD))[lane] = hv;
    }
}

// ---------------------------------------------------------------------------
// Kernels 2/3: fp32 GEMM, 128 x BN tile, BK=16, 256 threads, double-buffered
// smem with register prefetch, packed f32x2 accumulators.
// BN=128 -> 8x8 per thread; BN=64 -> 8x4 per thread.
// ---------------------------------------------------------------------------
template<int BN, bool RELU>
__global__ __launch_bounds__(256)
void gemm_kernel(const float* __restrict__ A,
                 const float* __restrict__ W,
                 const float* __restrict__ bias,
                 float* __restrict__ C,
                 int M, int Nn, int Ktot)
{
    constexpr int BM = 128, BK = 16;
    constexpr int TN  = BN / 16;
    constexpr int TN2 = TN / 2;
    constexpr int BV  = BN / 64;

    __shared__ float As[2][BK][BM + 4];
    __shared__ float Bs[2][BK][BN + 4];

    const int tid = threadIdx.x;
    const int tx  = tid & 15;
    const int ty  = tid >> 4;
    const int m0  = blockIdx.y * BM;
    const int n0  = blockIdx.x * BN;

    const int ar = tid >> 1;
    const int ac = (tid & 1) * 8;
    const bool a_ok = (m0 + ar) < M;
    const float* aptr = A + (size_t)(m0 + ar) * Ktot + ac;

    int brow[BV], bcol[BV];
#pragma unroll
    for (int t = 0; t < BV; ++t) {
        const int idx4 = tid + t * 256;
        brow[t] = idx4 / (BN / 4);
        bcol[t] = (idx4 % (BN / 4)) * 4;
    }

    u64 acc[8][TN2];
#pragma unroll
    for (int i = 0; i < 8; ++i)
#pragma unroll
        for (int j = 0; j < TN2; ++j) acc[i][j] = 0ull;

    float4 pa0 = make_float4(0,0,0,0), pa1 = pa0;
    float4 pb[BV];
    if (a_ok) { pa0 = *(const float4*)aptr; pa1 = *(const float4*)(aptr + 4); }
#pragma unroll
    for (int t = 0; t < BV; ++t)
        pb[t] = *(const float4*)(W + (size_t)brow[t] * Nn + n0 + bcol[t]);

    As[0][ac+0][ar] = pa0.x; As[0][ac+1][ar] = pa0.y;
    As[0][ac+2][ar] = pa0.z; As[0][ac+3][ar] = pa0.w;
    As[0][ac+4][ar] = pa1.x; As[0][ac+5][ar] = pa1.y;
    As[0][ac+6][ar] = pa1.z; As[0][ac+7][ar] = pa1.w;
#pragma unroll
    for (int t = 0; t < BV; ++t)
        *(float4*)&Bs[0][brow[t]][bcol[t]] = pb[t];
    __syncthreads();

    int buf = 0;
    for (int k0 = 0; k0 < Ktot; k0 += BK) {
        const int k1 = k0 + BK;
        const bool more = (k1 < Ktot);

        if (more) {
            if (a_ok) {
                pa0 = *(const float4*)(aptr + k1);
                pa1 = *(const float4*)(aptr + k1 + 4);
            }
#pragma unroll
            for (int t = 0; t < BV; ++t)
                pb[t] = *(const float4*)(W + (size_t)(k1 + brow[t]) * Nn + n0 + bcol[t]);
        }

#pragma unroll
        for (int kk = 0; kk < BK; ++kk) {
            float4 a0 = *(const float4*)&As[buf][kk][ty * 8];
            float4 a1 = *(const float4*)&As[buf][kk][ty * 8 + 4];
            const u64* bp = (const u64*)&Bs[buf][kk][tx * TN];
            u64 breg[TN2];
#pragma unroll
            for (int j = 0; j < TN2; ++j) breg[j] = bp[j];

            const float av[8] = {a0.x, a0.y, a0.z, a0.w, a1.x, a1.y, a1.z, a1.w};
#pragma unroll
            for (int i = 0; i < 8; ++i) {
                const u64 ad = dup2(av[i]);
#pragma unroll
                for (int j = 0; j < TN2; ++j) ffma2(acc[i][j], ad, breg[j]);
            }
        }

        if (more) {
            const int nb = buf ^ 1;
            As[nb][ac+0][ar] = pa0.x; As[nb][ac+1][ar] = pa0.y;
            As[nb][ac+2][ar] = pa0.z; As[nb][ac+3][ar] = pa0.w;
            As[nb][ac+4][ar] = pa1.x; As[nb][ac+5][ar] = pa1.y;
            As[nb][ac+6][ar] = pa1.z; As[nb][ac+7][ar] = pa1.w;
#pragma unroll
            for (int t = 0; t < BV; ++t)
                *(float4*)&Bs[nb][brow[t]][bcol[t]] = pb[t];
            __syncthreads();
            buf = nb;
        }
    }

    const int gn0 = n0 + tx * TN;
    float bsv[TN];
#pragma unroll
    for (int j = 0; j < TN; ++j) bsv[j] = bias[gn0 + j];

#pragma unroll
    for (int i = 0; i < 8; ++i) {
        const int gm = m0 + ty * 8 + i;
        if (gm >= M) continue;
        float o[TN];
#pragma unroll
        for (int j = 0; j < TN2; ++j) {
            float2 p = unpk(acc[i][j]);
            o[2*j]   = p.x + bsv[2*j];
            o[2*j+1] = p.y + bsv[2*j+1];
        }
        if (RELU) {
#pragma unroll
            for (int j = 0; j < TN; ++j) o[j] = fmaxf(o[j], 0.f);
        }
        float* cp = C + (size_t)gm * Nn + gn0;
#pragma unroll
        for (int j = 0; j < TN2; j += 2)
            *(float4*)(cp + j * 2) = make_float4(o[2*j], o[2*j+1], o[2*j+2], o[2*j+3]);
    }
}

// ---------------------------------------------------------------------------
// Kernel 4: partial S. Grid (4, B). Block (q,b) sums gs rows q*16..q*16+15.
// ---------------------------------------------------------------------------
__global__ void s_partial_kernel()
{
    const int q = blockIdx.x;
    const int b = blockIdx.y;
    const int h = threadIdx.x;
    const float* g = d_gs + (size_t)b * ROWS * GD;

    float s = 0.f;
#pragma unroll
    for (int j = q * 16; j < q * 16 + 16; ++j)
        s += g[(size_t)j * GD + h];
    d_Sp[((size_t)q * B_ + b) * GD + h] = s;
}

// ---------------------------------------------------------------------------
// Kernel 5: finalize. Grid (K+1, B), 256 threads.
// ---------------------------------------------------------------------------
__global__ void finalize_kernel(float* __restrict__ out)
{
    const int k = blockIdx.x;     // 0..K
    const int b = blockIdx.y;
    const int h = threadIdx.x;

    float S = d_Sp[((size_t)0 * B_ + b) * GD + h]
            + d_Sp[((size_t)1 * B_ + b) * GD + h]
            + d_Sp[((size_t)2 * B_ + b) * GD + h]
            + d_Sp[((size_t)3 * B_ + b) * GD + h];

    const float* g = d_gs + (size_t)b * ROWS * GD;

    float v;
    if (k < KC)
        v = S - g[(size_t)k * GD + h] + g[(size_t)(KC + k) * GD + h];
    else
        v = S + g[(size_t)(2 * KC) * GD + h];
    out[((size_t)b * (KC + 1) + k) * GD + h] = v;
}

// ---------------------------------------------------------------------------
extern "C" void kernel_launch(void* const* d_in, const int* in_sizes, int n_in,
                              void* d_out, int out_size)
{
    const float* hs = (const float*)d_in[0];
    const int*   cs = (const int*)  d_in[1];
    const float* W1 = (const float*)d_in[2];
    const float* b1 = (const float*)d_in[3];
    const float* W2 = (const float*)d_in[4];
    const float* b2 = (const float*)d_in[5];
    const int*   np = (const int*)  d_in[6];
    float* out = (float*)d_out;

    float *pH, *pH1, *pGS;
    cudaGetSymbolAddress((void**)&pH,  d_H);
    cudaGetSymbolAddress((void**)&pH1, d_h1);
    cudaGetSymbolAddress((void**)&pGS, d_gs);

    // idx0: mask
    mask_kernel<<<1, 256>>>(out);

    // idx1: clustered reduce + H materialization
    reduce_kernel<<<dim3(KC, B_), 512>>>(hs, cs, np);

    // idx2: layer 1 [4128,256]@[256,512]+b1, relu (128x128 tiles, 132 blocks)
    gemm_kernel<128, true ><<<dim3(GH / 128, (M_TOT + 127) / 128), 256>>>(pH,  W1, b1, pH1, M_TOT, GH, HD);

    // idx3: layer 2 [4128,512]@[512,256]+b2 (128x64 tiles, 132 blocks)  <- profiled slot
    gemm_kernel<64, false><<<dim3(GD / 64, (M_TOT + 127) / 128), 256>>>(pH1, W2, b2, pGS, M_TOT, GD, GH);

    // idx4: S partials
    s_partial_kernel<<<dim3(4, B_), 256>>>();

    // idx5: finalize
    finalize_kernel<<<dim3(KC + 1, B_), 256>>>(out);
}